// round 17
// baseline (speedup 1.0000x reference)
#include <cuda_runtime.h>
#include <cuda_fp16.h>

// Problem constants (fixed by the dataset)
#define HH   512
#define WW   1024
#define HOo  512
#define WOo  1024
#define NPIX (HH * WW)          // 524288 input pixels
#define NOUT (HOo * WOo)        // 524288 output cells per plane
#define NPLANE 128              // B*C
#define CPW  2                  // cells per warp (consecutive in x)
#define CELLS_PB 16             // 8 warps x 2 cells per block (one row segment)
#define ROWSLAB 2048            // fixed entry slab per output row (mean ~1024, max ~1150)

// ---- static device scratch ----
__device__ __half g_xt[(size_t)NPIX * NPLANE]; // 128MB transposed x [pixel][plane], fp16
__device__ int    g_count[NOUT];               // zero at start; scanA re-zeroes each run
__device__ int    g_off[NOUT];                 // row-local exclusive scan
__device__ int    g_cursor[NOUT];
__device__ int4   g_entry[512 * ROWSLAB];      // 16MB slab-allocated entries

// ---------------------------------------------------------------
// K1a: transpose only (hist un-fused so it can run on a parallel stream).
__global__ __launch_bounds__(256)
void tx_k(const float* __restrict__ x) {
    __shared__ __half hbuf[64][132];            // stride 132: uint2-aligned, low conflict
    int p0 = blockIdx.x * 64;
    int tid = threadIdx.x;

    #pragma unroll
    for (int it = 0; it < 32; it++) {
        int idx = tid + it * 256;               // 0..8191
        int c  = idx >> 6;                      // plane 0..127
        int px = idx & 63;
        hbuf[px][c] = __float2half(__ldcs(&x[(size_t)c * NPIX + p0 + px]));
    }
    __syncthreads();

    int lane = tid & 31, wid = tid >> 5;
    #pragma unroll
    for (int i = wid; i < 64; i += 8) {
        uint2 v = *reinterpret_cast<uint2*>(&hbuf[i][lane * 4]);
        *reinterpret_cast<uint2*>(&g_xt[(size_t)(p0 + i) * NPLANE + lane * 4]) = v;
    }
}

// K1b: histogram — one entry per pixel, binned by anchor (floor) cell.
__global__ __launch_bounds__(256)
void hist_k(const float2* __restrict__ smap) {
    int p = blockIdx.x * blockDim.x + threadIdx.x;
    if (p >= NPIX) return;
    float2 s = __ldg(&smap[p]);
    int x0 = (int)floorf(s.x);
    int y0 = (int)floorf(s.y);
    atomicAdd(&g_count[(y0 << 10) + x0], 1);
}

// K2: per-row exclusive scan -> row-local offsets + cursors; self-cleaning.
__global__ __launch_bounds__(1024)
void scanA_k() {
    int tid = threadIdx.x;
    int cell = blockIdx.x * 1024 + tid;
    int cnt = g_count[cell];
    g_count[cell] = 0;
    int lane = tid & 31, wid = tid >> 5;
    int v = cnt;
    #pragma unroll
    for (int d = 1; d < 32; d <<= 1) {
        int t = __shfl_up_sync(0xFFFFFFFFu, v, d);
        if (lane >= d) v += t;
    }
    __shared__ int wsum[32];
    if (lane == 31) wsum[wid] = v;
    __syncthreads();
    if (wid == 0) {
        int s = wsum[lane];
        #pragma unroll
        for (int d = 1; d < 32; d <<= 1) {
            int t = __shfl_up_sync(0xFFFFFFFFu, s, d);
            if (lane >= d) s += t;
        }
        wsum[lane] = s;
    }
    __syncthreads();
    int excl = v - cnt + (wid ? wsum[wid - 1] : 0);
    g_off[cell] = excl;
    g_cursor[cell] = excl;
}

// K3: scatter one entry per pixel into its row slab.
__global__ __launch_bounds__(256)
void scatter_k(const float2* __restrict__ smap) {
    int p = blockIdx.x * blockDim.x + threadIdx.x;
    if (p >= NPIX) return;
    float2 s = __ldcs(&smap[p]);
    float x0f = floorf(s.x), y0f = floorf(s.y);
    int x0 = (int)x0f, y0 = (int)y0f;
    float wx = s.x - x0f, wy = s.y - y0f;
    int pos = atomicAdd(&g_cursor[(y0 << 10) + x0], 1) + (y0 << 11);
    __stcs(&g_entry[pos], make_int4(x0, p, __float_as_int(wx), __float_as_int(wy)));
}

// K4: gather — unchanged from the R16 best.
__global__ __launch_bounds__(256)
void gather_k(float* __restrict__ out) {
    __shared__ float acc_s[CELLS_PB][NPLANE + 4];   // 528B stride: float4-aligned
    __shared__ int   s_off[8][4];                   // per warp: beg0,end0,beg1,end1
    __shared__ int4  s_meta[8][32];                 // warp-private staged entries
    int tid = threadIdx.x;
    int lane = tid & 31, wid = tid >> 5;            // 8 warps
    int cell0 = blockIdx.x * CELLS_PB;              // 16-aligned -> one row
    int cy = cell0 >> 10;
    int cx0 = (cell0 & 1023) + wid * CPW;

    // Phase A: cooperative g_off prefetch (8 warps x {beg0,end0,beg1,end1})
    if (tid < 32) {
        int w = tid >> 2, q = tid & 3;
        int rr = q >> 1, side = q & 1;
        int ay = cy - 1 + rr;
        int val = 0;
        if ((unsigned)ay <= (unsigned)(HOo - 2)) {  // anchor rows 0..510
            int cxw = (cell0 & 1023) + w * CPW;
            int xsw = max(cxw - 1, 0);
            int xew = min(cxw + CPW - 1, WOo - 2);
            int col = side ? (xew + 1) : xsw;
            val = __ldg(&g_off[(ay << 10) + col]) + (ay << 11);
        }
        s_off[w][q] = val;
    }
    __syncthreads();

    int beg0 = s_off[wid][0], end0 = s_off[wid][1];
    int beg1 = s_off[wid][2], end1 = s_off[wid][3];
    int n0 = end0 - beg0, n1 = end1 - beg1;
    int total = n0 + n1;
    int tclamp = min(total, 32);

    // Phase B: stage entries (lane l -> entry l), fold y-weight, pad with
    // zero-weight dummies so the hot loop needs no guards.
    {
        int4 e = make_int4(cx0, 0, 0, 0);           // dummy: pixel 0, weight 0
        if (lane < tclamp) {
            bool r0 = lane < n0;                    // row cy-1 -> weight wy
            int gi = r0 ? (beg0 + lane) : (beg1 + lane - n0);
            e = __ldcs(&g_entry[gi]);
            float wy = __int_as_float(e.w);
            e.w = __float_as_int(r0 ? wy : (1.0f - wy));
        }
        s_meta[wid][lane] = e;
    }
    __syncwarp();

    float a0[4] = {0.f, 0.f, 0.f, 0.f};             // cell cx0
    float a1[4] = {0.f, 0.f, 0.f, 0.f};             // cell cx0+1

    auto process = [&](int4 e, uint2 r) {
        float wx = __int_as_float(e.z);
        float wyv = __int_as_float(e.w);
        float omx = 1.0f - wx;
        int d = e.x - cx0;                          // -1, 0, 1
        float w0 = (d == 0) ? omx : ((d == -1) ? wx : 0.0f);
        float w1 = (d == 1) ? omx : ((d == 0) ? wx : 0.0f);
        w0 *= wyv;
        w1 *= wyv;
        float2 f0 = __half22float2(*reinterpret_cast<__half2*>(&r.x));
        float2 f1 = __half22float2(*reinterpret_cast<__half2*>(&r.y));
        a0[0] = fmaf(w0, f0.x, a0[0]);
        a0[1] = fmaf(w0, f0.y, a0[1]);
        a0[2] = fmaf(w0, f1.x, a0[2]);
        a0[3] = fmaf(w0, f1.y, a0[3]);
        a1[0] = fmaf(w1, f0.x, a1[0]);
        a1[1] = fmaf(w1, f0.y, a1[1]);
        a1[2] = fmaf(w1, f1.x, a1[2]);
        a1[3] = fmaf(w1, f1.y, a1[3]);
    };

    // Phase C: 4-wide chunks; metas from smem (broadcast), 4 rows in flight.
    int nproc = (tclamp + 3) & ~3;                  // <= 32; dummies are 0-weight
    #pragma unroll 1
    for (int base = 0; base < nproc; base += 4) {
        int4 e0 = s_meta[wid][base];
        int4 e1 = s_meta[wid][base + 1];
        int4 e2 = s_meta[wid][base + 2];
        int4 e3 = s_meta[wid][base + 3];
        uint2 r0 = __ldg(reinterpret_cast<const uint2*>(
            &g_xt[(size_t)e0.y * NPLANE + lane * 4]));
        uint2 r1 = __ldg(reinterpret_cast<const uint2*>(
            &g_xt[(size_t)e1.y * NPLANE + lane * 4]));
        uint2 r2 = __ldg(reinterpret_cast<const uint2*>(
            &g_xt[(size_t)e2.y * NPLANE + lane * 4]));
        uint2 r3 = __ldg(reinterpret_cast<const uint2*>(
            &g_xt[(size_t)e3.y * NPLANE + lane * 4]));
        process(e0, r0);
        process(e1, r1);
        process(e2, r2);
        process(e3, r3);
    }

    // astronomically-rare tail (total > 32): direct fallback
    #pragma unroll 1
    for (int k = 32; k < total; k++) {
        bool r0k = k < n0;
        int gi = r0k ? (beg0 + k) : (beg1 + k - n0);
        int4 e = __ldcs(&g_entry[gi]);
        float wy = __int_as_float(e.w);
        e.w = __float_as_int(r0k ? wy : (1.0f - wy));
        uint2 r = __ldg(reinterpret_cast<const uint2*>(
            &g_xt[(size_t)e.y * NPLANE + lane * 4]));
        process(e, r);
    }

    // stage to shared (plane = lane*4 + r), then coalesced streaming writeout
    {
        int ci = wid * CPW;
        *reinterpret_cast<float4*>(&acc_s[ci][lane * 4]) =
            make_float4(a0[0], a0[1], a0[2], a0[3]);
        *reinterpret_cast<float4*>(&acc_s[ci + 1][lane * 4]) =
            make_float4(a1[0], a1[1], a1[2], a1[3]);
    }
    __syncthreads();

    for (int idx = tid; idx < CELLS_PB * NPLANE; idx += 256) {
        int plane = idx >> 4;                       // 16 cells per segment
        int ci = idx & (CELLS_PB - 1);
        __stcs(&out[(size_t)plane * NOUT + cell0 + ci], acc_s[ci][plane]);
    }
}

// ---------------------------------------------------------------
// Fork-join: the transpose (BW-bound) and the binning chain
// (hist->scanA->scatter, atomic/latency-bound) are independent; run them
// concurrently and join before the gather. Capture-legal pattern:
// event-record on the capture (default) stream -> side stream waits ->
// side stream rejoins via second event before the gather.
extern "C" void kernel_launch(void* const* d_in, const int* in_sizes, int n_in,
                              void* d_out, int out_size) {
    const float*  x    = (const float*)d_in[0];
    const float2* smap = (const float2*)d_in[1];
    float*        out  = (float*)d_out;

    static cudaStream_t s2 = nullptr;
    static cudaEvent_t evFork = nullptr, evJoin = nullptr;
    if (s2 == nullptr) {
        cudaStreamCreateWithFlags(&s2, cudaStreamNonBlocking);
        cudaEventCreateWithFlags(&evFork, cudaEventDisableTiming);
        cudaEventCreateWithFlags(&evJoin, cudaEventDisableTiming);
    }

    // fork: side stream inherits capture-stream dependencies
    cudaEventRecord(evFork, 0);
    cudaStreamWaitEvent(s2, evFork, 0);

    // side stream: binning chain (no dependency on the transpose)
    hist_k<<<NPIX / 256, 256, 0, s2>>>(smap);
    scanA_k<<<512, 1024, 0, s2>>>();
    scatter_k<<<NPIX / 256, 256, 0, s2>>>(smap);
    cudaEventRecord(evJoin, s2);

    // main stream: transpose, concurrent with the binning chain
    tx_k<<<NPIX / 64, 256>>>(x);

    // join, then gather (needs g_xt + entries + offsets)
    cudaStreamWaitEvent(0, evJoin, 0);
    gather_k<<<NOUT / CELLS_PB, 256>>>(out);
}